// round 7
// baseline (speedup 1.0000x reference)
#include <cuda_runtime.h>
#include <cstdint>
#include <cstddef>

#define NB 64
typedef unsigned long long ull;

__device__ __forceinline__ ull pack2(float x) {
    ull d; unsigned u = __float_as_uint(x);
    asm("mov.b64 %0, {%1, %1};" : "=l"(d) : "r"(u));
    return d;
}
__device__ __forceinline__ ull fma2(ull a, ull b, ull c) {
    ull d;
    asm("fma.rn.f32x2 %0, %1, %2, %3;" : "=l"(d) : "l"(a), "l"(b), "l"(c));
    return d;
}
__device__ __forceinline__ void unpack2(ull a, float& lo, float& hi) {
    unsigned l, h;
    asm("mov.b64 {%0, %1}, %2;" : "=r"(l), "=r"(h) : "l"(a));
    lo = __uint_as_float(l); hi = __uint_as_float(h);
}

__device__ float g_h1[(size_t)NB * 128 * 64 * 64];
__device__ float g_h2[(size_t)NB * 128 * 32 * 32];
__device__ float g_ze[(size_t)NB * 64 * 32 * 32];
__device__ float g_zq[(size_t)NB * 64 * 32 * 32];
__device__ float g_d1[(size_t)NB * 128 * 64 * 64];
__device__ float g_d2[(size_t)NB * 128 * 128 * 128];
__device__ float g_vq_part[256];
__device__ float g_rec_part[4096];
__device__ float g_w1t[16 * 3 * 128];     // [kk][ci][co]
__device__ float g_w2t[16 * 128 * 128];   // [kk][ci][co]
__device__ float g_w3t[9 * 128 * 64];     // [kk][ci][co]
__device__ float g_dw1t[64 * 16 * 128];   // [ci][kk][co]
__device__ float g_dw2t[128 * 16 * 128];  // [ci][kk][co]
__device__ float g_w3dt[128 * 9 * 3];     // [ci*9+kk][co]

__global__ void wprep_k(const float* __restrict__ w1, const float* __restrict__ w2,
                        const float* __restrict__ w3, const float* __restrict__ dw1,
                        const float* __restrict__ dw2, const float* __restrict__ dw3)
{
    int st = gridDim.x * blockDim.x, g = blockIdx.x * blockDim.x + threadIdx.x;
    for (int t = g; t < 16 * 3 * 128; t += st) {
        int co = t & 127, r = t >> 7, ci = r % 3, kk = r / 3;
        g_w1t[(kk * 3 + ci) * 128 + co] = w1[((size_t)co * 3 + ci) * 16 + kk];
    }
    for (int t = g; t < 16 * 128 * 128; t += st) {
        int co = t & 127, r = t >> 7, ci = r & 127, kk = r >> 7;
        g_w2t[(kk * 128 + ci) * 128 + co] = w2[((size_t)co * 128 + ci) * 16 + kk];
    }
    for (int t = g; t < 9 * 128 * 64; t += st) {
        int co = t & 63, r = t >> 6, ci = r & 127, kk = r >> 7;
        g_w3t[(kk * 128 + ci) * 64 + co] = w3[((size_t)co * 128 + ci) * 9 + kk];
    }
    for (int t = g; t < 64 * 16 * 128; t += st) {
        int co = t & 127, r = t >> 7, kk = r & 15, ci = r >> 4;
        g_dw1t[t] = dw1[((size_t)ci * 128 + co) * 16 + kk];
    }
    for (int t = g; t < 128 * 16 * 128; t += st) {
        int co = t & 127, r = t >> 7, kk = r & 15, ci = r >> 4;
        g_dw2t[t] = dw2[((size_t)ci * 128 + co) * 16 + kk];
    }
    for (int t = g; t < 128 * 9 * 3; t += st) {
        int co = t % 3, r = t / 3, kk = r % 9, ci = r / 9;
        g_w3dt[t] = dw3[((size_t)co * 128 + ci) * 9 + kk];
    }
}

// enc1 (CIN=3): bit-exact scalar chain kernel (unchanged).
template <int K, int S, int CIN, int COUT, int H, bool RELU>
__global__ void __launch_bounds__(512) conv_seq(const float* __restrict__ in,
                                                const float* __restrict__ wt,
                                                const float* __restrict__ bias,
                                                float* __restrict__ out)
{
    constexpr int W = H, OH = (H + 2 - K) / S + 1, OW = OH;
    constexpr int IHS = 7 * S + K, IWS = 7 * S + K, IWP = IWS + 1;
    constexpr int SW_OFF = ((CIN * IHS * IWP + 3) / 4) * 4;
    extern __shared__ float sm[];
    float* s_in = sm;
    float* s_w  = sm + SW_OFF;
    const int n = blockIdx.z, co0 = blockIdx.y * 64;
    constexpr int TWn = OW / 8;
    const int oh0 = (blockIdx.x / TWn) * 8, ow0 = (blockIdx.x % TWn) * 8;
    const int tid = threadIdx.x, px = tid & 63, cog = tid >> 6;
    const int ohr = px >> 3, owr = px & 7;
    const int ihb = oh0 * S - 1, iwb = ow0 * S - 1;

    for (int t = tid; t < CIN * IHS * IWS; t += 512) {
        int ci = t / (IHS * IWS), r = t % (IHS * IWS), rr = r / IWS, cc = r % IWS;
        int ih = ihb + rr, iw = iwb + cc;
        float v = 0.f;
        if (ih >= 0 && ih < H && iw >= 0 && iw < W)
            v = in[(((size_t)n * CIN + ci) * H + ih) * W + iw];
        s_in[(ci * IHS + rr) * IWP + cc] = v;
    }
    const int cob = co0 + cog * 8;
    float a[8];
    #pragma unroll
    for (int i = 0; i < 8; i++) a[i] = 0.f;
    #pragma unroll
    for (int kh = 0; kh < K; kh++)
    #pragma unroll
    for (int kw = 0; kw < K; kw++) {
        __syncthreads();
        for (int t = tid; t < CIN * 64; t += 512)
            s_w[t] = wt[(size_t)((kh * K + kw) * CIN + (t >> 6)) * COUT + co0 + (t & 63)];
        __syncthreads();
        const float* ip = &s_in[(ohr * S + kh) * IWP + owr * S + kw];
        const float* wp = &s_w[cog * 8];
        #pragma unroll 3
        for (int ci = 0; ci < CIN; ci++) {
            float iv = ip[ci * IHS * IWP];
            float4 w0 = *(const float4*)&wp[ci * 64];
            float4 w1 = *(const float4*)&wp[ci * 64 + 4];
            a[0] = __fmaf_rn(iv, w0.x, a[0]);
            a[1] = __fmaf_rn(iv, w0.y, a[1]);
            a[2] = __fmaf_rn(iv, w0.z, a[2]);
            a[3] = __fmaf_rn(iv, w0.w, a[3]);
            a[4] = __fmaf_rn(iv, w1.x, a[4]);
            a[5] = __fmaf_rn(iv, w1.y, a[5]);
            a[6] = __fmaf_rn(iv, w1.z, a[6]);
            a[7] = __fmaf_rn(iv, w1.w, a[7]);
        }
    }
    const int oh = oh0 + ohr, ow = ow0 + owr;
    #pragma unroll
    for (int c = 0; c < 8; c++) {
        float v = __fadd_rn(a[c], bias[cob + c]);
        if (RELU) v = fmaxf(v, 0.f);
        out[(((size_t)n * COUT + cob + c) * OH + oh) * OW + ow] = v;
    }
}

// enc2: 128->128 k4s2 relu. f32x2, same op order as R6; panel prefetch added.
__global__ void __launch_bounds__(512) enc2_k(const float* __restrict__ in,
                                              const float* __restrict__ wt,
                                              const float* __restrict__ bias,
                                              float* __restrict__ out)
{
    extern __shared__ float sm[];
    float* s_in = sm;                 // [128][18][19]
    float* s_w  = sm + 128 * 18 * 19; // [64ci][128co]
    const int n = blockIdx.z;
    const int oh0 = (blockIdx.x >> 2) * 8, ow0 = (blockIdx.x & 3) * 8;
    const int tid = threadIdx.x, px = tid & 31, cog = tid >> 5;
    const int ohr = px >> 2, owp = px & 3;
    const int ihb = oh0 * 2 - 1, iwb = ow0 * 2 - 1;

    for (int t = tid; t < 128 * 18 * 18; t += 512) {
        int ci = t / 324, r = t % 324, rr = r / 18, cc = r % 18;
        int ih = ihb + rr, iw = iwb + cc;
        float v = 0.f;
        if (ih >= 0 && ih < 64 && iw >= 0 && iw < 64)
            v = in[(((size_t)n * 128 + ci) * 64 + ih) * 64 + iw];
        s_in[(ci * 18 + rr) * 19 + cc] = v;
    }

    const float4* wt4 = (const float4*)wt;
    float4* sw4 = (float4*)s_w;
    float4 pw[4];
    #pragma unroll
    for (int k = 0; k < 4; k++) pw[k] = wt4[tid + k * 512];

    ull a[2][4];
    #pragma unroll
    for (int p = 0; p < 2; p++)
    #pragma unroll
    for (int j = 0; j < 4; j++) a[p][j] = 0ull;

    for (int p = 0; p < 32; p++) {
        __syncthreads();
        #pragma unroll
        for (int k = 0; k < 4; k++) sw4[tid + k * 512] = pw[k];
        __syncthreads();
        if (p < 31) {
            #pragma unroll
            for (int k = 0; k < 4; k++) pw[k] = wt4[(size_t)(p + 1) * 2048 + tid + k * 512];
        }
        const int kh = p >> 3, kw = (p >> 1) & 3, ci0 = (p & 1) * 64;
        const float* ip = &s_in[((ci0 * 18) + ohr * 2 + kh) * 19 + owp * 4 + kw];
        const float* wp = &s_w[cog * 8];
        #pragma unroll 2
        for (int ci = 0; ci < 64; ci++) {
            float i0 = ip[ci * 342];
            float i1 = ip[ci * 342 + 2];
            ull p0 = pack2(i0), p1 = pack2(i1);
            ulonglong2 wA = *(const ulonglong2*)&wp[ci * 128];
            ulonglong2 wB = *(const ulonglong2*)&wp[ci * 128 + 4];
            a[0][0] = fma2(p0, wA.x, a[0][0]);
            a[0][1] = fma2(p0, wA.y, a[0][1]);
            a[0][2] = fma2(p0, wB.x, a[0][2]);
            a[0][3] = fma2(p0, wB.y, a[0][3]);
            a[1][0] = fma2(p1, wA.x, a[1][0]);
            a[1][1] = fma2(p1, wA.y, a[1][1]);
            a[1][2] = fma2(p1, wB.x, a[1][2]);
            a[1][3] = fma2(p1, wB.y, a[1][3]);
        }
    }
    const int oh = oh0 + ohr;
    #pragma unroll
    for (int p = 0; p < 2; p++) {
        int ow = ow0 + owp * 2 + p;
        #pragma unroll
        for (int j = 0; j < 4; j++) {
            int co = cog * 8 + 2 * j;
            float lo, hi;
            unpack2(a[p][j], lo, hi);
            out[(((size_t)n * 128 + co) * 32 + oh) * 32 + ow] =
                fmaxf(__fadd_rn(lo, bias[co]), 0.f);
            out[(((size_t)n * 128 + co + 1) * 32 + oh) * 32 + ow] =
                fmaxf(__fadd_rn(hi, bias[co + 1]), 0.f);
        }
    }
}

// enc3: 128->64 k3s1. 512 thr = 64px x 8cog, panel prefetch, 2 blocks/SM.
__global__ void __launch_bounds__(512) enc3_k(const float* __restrict__ in,
                                              const float* __restrict__ wt,
                                              const float* __restrict__ bias,
                                              float* __restrict__ out)
{
    extern __shared__ float sm[];
    float* s_in = sm;                 // [128][10][13]
    float* s_w  = sm + 128 * 10 * 13; // [128ci][64co]
    const int n = blockIdx.z;
    const int oh0 = (blockIdx.x >> 2) * 8, ow0 = (blockIdx.x & 3) * 8;
    const int tid = threadIdx.x, px = tid & 63, cog = tid >> 6;
    const int ohr = px >> 3, owr = px & 7;
    const int ihb = oh0 - 1, iwb = ow0 - 1;

    for (int t = tid; t < 128 * 10 * 10; t += 512) {
        int ci = t / 100, r = t % 100, rr = r / 10, cc = r % 10;
        int ih = ihb + rr, iw = iwb + cc;
        float v = 0.f;
        if (ih >= 0 && ih < 32 && iw >= 0 && iw < 32)
            v = in[(((size_t)n * 128 + ci) * 32 + ih) * 32 + iw];
        s_in[(ci * 10 + rr) * 13 + cc] = v;
    }

    const float4* wt4 = (const float4*)wt;
    float4* sw4 = (float4*)s_w;
    float4 pw[4];
    #pragma unroll
    for (int k = 0; k < 4; k++) pw[k] = wt4[tid + k * 512];

    ull a[4];
    #pragma unroll
    for (int j = 0; j < 4; j++) a[j] = 0ull;

    for (int p = 0; p < 9; p++) {
        __syncthreads();
        #pragma unroll
        for (int k = 0; k < 4; k++) sw4[tid + k * 512] = pw[k];
        __syncthreads();
        if (p < 8) {
            #pragma unroll
            for (int k = 0; k < 4; k++) pw[k] = wt4[(size_t)(p + 1) * 2048 + tid + k * 512];
        }
        const int kh = p / 3, kw = p % 3;
        const float* ip = &s_in[(ohr + kh) * 13 + owr + kw];
        const float* wp = &s_w[cog * 8];
        #pragma unroll 4
        for (int ci = 0; ci < 128; ci++) {
            float iv = ip[ci * 130];
            ull pk = pack2(iv);
            ulonglong2 uA = *(const ulonglong2*)&wp[ci * 64];
            ulonglong2 uB = *(const ulonglong2*)&wp[ci * 64 + 4];
            a[0] = fma2(pk, uA.x, a[0]);
            a[1] = fma2(pk, uA.y, a[1]);
            a[2] = fma2(pk, uB.x, a[2]);
            a[3] = fma2(pk, uB.y, a[3]);
        }
    }
    const int oh = oh0 + ohr, ow = ow0 + owr;
    #pragma unroll
    for (int j = 0; j < 4; j++) {
        int co = cog * 8 + 2 * j;
        float lo, hi;
        unpack2(a[j], lo, hi);
        out[(((size_t)n * 64 + co) * 32 + oh) * 32 + ow] = __fadd_rn(lo, bias[co]);
        out[(((size_t)n * 64 + co + 1) * 32 + oh) * 32 + ow] = __fadd_rn(hi, bias[co + 1]);
    }
}

// VQ (unchanged bit-exact numerics).
__global__ void __launch_bounds__(256) vq_k(const float* __restrict__ ze,
                                            const float* __restrict__ cb,
                                            float* __restrict__ zq,
                                            float* __restrict__ part)
{
    extern __shared__ float sm[];
    float* s_cb  = sm;
    float* s_cb2 = sm + 32768;
    __shared__ float red[256];
    const int tid = threadIdx.x;
    for (int t = tid; t < 32768; t += 256) s_cb[t] = cb[t];
    __syncthreads();
    for (int k = tid; k < 512; k += 256) {
        float s = 0.f;
        for (int d = 0; d < 64; d++) {
            float c = s_cb[k * 64 + d];
            s = __fadd_rn(s, __fmul_rn(c, c));
        }
        s_cb2[k] = s;
    }
    __syncthreads();

    const int v = blockIdx.x * 256 + tid;
    const int n = v >> 10, hw = v & 1023;
    const float* zp = ze + (size_t)n * 64 * 1024 + hw;
    float z[64];
    #pragma unroll
    for (int d = 0; d < 64; d++) z[d] = zp[(size_t)d * 1024];

    float z2 = 0.f;
    #pragma unroll
    for (int d = 0; d < 64; d++) z2 = __fadd_rn(z2, __fmul_rn(z[d], z[d]));

    float best = 3.4e38f;
    int bi = 0;
    for (int k0 = 0; k0 < 512; k0 += 4) {
        float dt0 = 0.f, dt1 = 0.f, dt2 = 0.f, dt3 = 0.f;
        const float* c0 = &s_cb[(k0 + 0) * 64];
        const float* c1 = &s_cb[(k0 + 1) * 64];
        const float* c2 = &s_cb[(k0 + 2) * 64];
        const float* c3 = &s_cb[(k0 + 3) * 64];
        #pragma unroll
        for (int d = 0; d < 64; d++) {
            float zd = z[d];
            dt0 = __fmaf_rn(zd, c0[d], dt0);
            dt1 = __fmaf_rn(zd, c1[d], dt1);
            dt2 = __fmaf_rn(zd, c2[d], dt2);
            dt3 = __fmaf_rn(zd, c3[d], dt3);
        }
        float s0 = __fsub_rn(__fadd_rn(z2, s_cb2[k0 + 0]), __fmul_rn(2.f, dt0));
        float s1 = __fsub_rn(__fadd_rn(z2, s_cb2[k0 + 1]), __fmul_rn(2.f, dt1));
        float s2 = __fsub_rn(__fadd_rn(z2, s_cb2[k0 + 2]), __fmul_rn(2.f, dt2));
        float s3 = __fsub_rn(__fadd_rn(z2, s_cb2[k0 + 3]), __fmul_rn(2.f, dt3));
        if (s0 < best) { best = s0; bi = k0; }
        if (s1 < best) { best = s1; bi = k0 + 1; }
        if (s2 < best) { best = s2; bi = k0 + 2; }
        if (s3 < best) { best = s3; bi = k0 + 3; }
    }

    float* zqp = zq + (size_t)n * 64 * 1024 + hw;
    float lsum = 0.f;
    #pragma unroll
    for (int d = 0; d < 64; d++) {
        float c = s_cb[bi * 64 + d];
        float df = z[d] - c;
        lsum = fmaf(df, df, lsum);
        zqp[(size_t)d * 1024] = __fadd_rn(z[d], __fsub_rn(c, z[d]));
    }
    red[tid] = lsum;
    __syncthreads();
    for (int s = 128; s > 0; s >>= 1) {
        if (tid < s) red[tid] += red[tid + s];
        __syncthreads();
    }
    if (tid == 0) part[blockIdx.x] = red[0];
}

// ConvTranspose2d k4s2p1 + bias + relu, f32x2 co-packed. wtt: [ci][kk][co].
// Block: 16oh x 8ow x 64co, 256 thr, 3 blocks/SM. Thread: 2x2 quad x 8co.
template <int CIN, int COUT, int IH>
__global__ void __launch_bounds__(256, 3) deconv_k(const float* __restrict__ in,
                                                   const float* __restrict__ wtt,
                                                   const float* __restrict__ bias,
                                                   float* __restrict__ out)
{
    constexpr int IW = IH, OH = IH * 2, OW = IW * 2;
    constexpr int OWT = OW / 8;
    extern __shared__ float sm[];
    float* s_in = sm;                 // [16][10][8]
    float* s_w  = sm + 16 * 10 * 8;   // [16ci*16kk][64co]
    const int n = blockIdx.z, co0 = blockIdx.y * 64;
    const int oh0 = (blockIdx.x / OWT) * 16, ow0 = (blockIdx.x % OWT) * 8;
    const int tid = threadIdx.x;
    const int qc = tid & 3, qr = (tid >> 2) & 7, cog = tid >> 5;
    const int ihb = oh0 / 2 - 1, iwb = ow0 / 2 - 1;

    ull a[2][2][4];
    #pragma unroll
    for (int i = 0; i < 2; i++)
    #pragma unroll
    for (int j = 0; j < 2; j++)
    #pragma unroll
    for (int c = 0; c < 4; c++) a[i][j][c] = 0ull;

    const float4* wtt4 = (const float4*)wtt;
    float4* sw4 = (float4*)s_w;

    for (int ci0 = 0; ci0 < CIN; ci0 += 16) {
        for (int t = tid; t < 16 * 10 * 6; t += 256) {
            int c = t / 60, r = (t % 60) / 6, cc = t % 6;
            int ih = ihb + r, iw = iwb + cc;
            float v = 0.f;
            if (ih >= 0 && ih < IH && iw >= 0 && iw < IW)
                v = in[(((size_t)n * CIN + ci0 + c) * IH + ih) * IW + iw];
            s_in[(c * 10 + r) * 8 + cc] = v;
        }
        #pragma unroll
        for (int k = 0; k < 16; k++) {
            int idx = tid + k * 256;
            int row = idx >> 4, col4 = idx & 15;
            sw4[idx] = wtt4[(size_t)(ci0 * 16 + row) * (COUT / 4) + (co0 >> 2) + col4];
        }
        __syncthreads();

        for (int cil = 0; cil < 16; cil++) {
            const float* bp = &s_in[(cil * 10 + qr) * 8 + qc];
            ull ivd[3][3];
            #pragma unroll
            for (int r = 0; r < 3; r++)
            #pragma unroll
            for (int c = 0; c < 3; c++) ivd[r][c] = pack2(bp[r * 8 + c]);

            const float* wb = &s_w[cil * 1024 + cog * 8];
            #pragma unroll
            for (int kk = 0; kk < 16; kk++) {
                const int kh = kk >> 2, kw = kk & 3;
                const int r  = 2 - ((kh + 1) >> 1);
                const int c  = 2 - ((kw + 1) >> 1);
                const int dh = 1 - (kh & 1);
                const int pw = 1 - (kw & 1);
                ulonglong2 uA = *(const ulonglong2*)&wb[kk * 64];
                ulonglong2 uB = *(const ulonglong2*)&wb[kk * 64 + 4];
                ull iv = ivd[r][c];
                ull* ap = a[dh][pw];
                ap[0] = fma2(iv, uA.x, ap[0]);
                ap[1] = fma2(iv, uA.y, ap[1]);
                ap[2] = fma2(iv, uB.x, ap[2]);
                ap[3] = fma2(iv, uB.y, ap[3]);
            }
        }
        __syncthreads();
    }

    #pragma unroll
    for (int j = 0; j < 4; j++) {
        int co = co0 + cog * 8 + 2 * j;
        float b0 = bias[co], b1 = bias[co + 1];
        #pragma unroll
        for (int dh = 0; dh < 2; dh++) {
            int oh = oh0 + 2 * qr + dh;
            float e0, e1, o0, o1;
            unpack2(a[dh][0][j], e0, e1);
            unpack2(a[dh][1][j], o0, o1);
            float2 v0 = {fmaxf(e0 + b0, 0.f), fmaxf(o0 + b0, 0.f)};
            float2 v1 = {fmaxf(e1 + b1, 0.f), fmaxf(o1 + b1, 0.f)};
            *(float2*)&out[(((size_t)n * COUT + co) * OH + oh) * OW + ow0 + 2 * qc] = v0;
            *(float2*)&out[(((size_t)n * COUT + co + 1) * OH + oh) * OW + ow0 + 2 * qc] = v1;
        }
    }
}

// dec3 + recon-MSE partial; float4 weight loads.
__global__ void __launch_bounds__(256) dec3_k(const float* __restrict__ in,
                                              const float* __restrict__ wtt,
                                              const float* __restrict__ bias,
                                              const float* __restrict__ x,
                                              float* __restrict__ out,
                                              float* __restrict__ rec_part)
{
    extern __shared__ float sm[];
    float* s_in = sm;
    float* s_w  = sm + 16 * 4 * 130;
    __shared__ float red[256];
    const int n = blockIdx.y, oh0 = blockIdx.x * 2;
    const int tid = threadIdx.x, r = tid >> 7, col = tid & 127, oh = oh0 + r;

    for (int t = tid; t < 128 * 9 * 3; t += 256)
        s_w[(t / 3) * 4 + t % 3] = wtt[t];

    float a0 = 0.f, a1 = 0.f, a2 = 0.f;
    for (int ci0 = 0; ci0 < 128; ci0 += 16) {
        for (int t = tid; t < 16 * 4 * 130; t += 256) {
            int cil = t / 520, r2 = t % 520, rr = r2 / 130, cc = r2 % 130;
            int ih = oh0 - 1 + rr, iw = cc - 1;
            float v = 0.f;
            if (ih >= 0 && ih < 128 && iw >= 0 && iw < 128)
                v = in[(((size_t)n * 128 + ci0 + cil) * 128 + ih) * 128 + iw];
            s_in[t] = v;
        }
        __syncthreads();
        for (int cil = 0; cil < 16; cil++) {
            #pragma unroll
            for (int kh = 0; kh < 3; kh++) {
                const float* rp = &s_in[(cil * 4 + r + kh) * 130 + col];
                #pragma unroll
                for (int kw = 0; kw < 3; kw++) {
                    float iv = rp[kw];
                    float4 wv = *(const float4*)&s_w[((ci0 + cil) * 9 + kh * 3 + kw) * 4];
                    a0 = fmaf(wv.x, iv, a0);
                    a1 = fmaf(wv.y, iv, a1);
                    a2 = fmaf(wv.z, iv, a2);
                }
            }
        }
        __syncthreads();
    }
    float lsum = 0.f;
    float accs[3] = {a0, a1, a2};
    #pragma unroll
    for (int co = 0; co < 3; co++) {
        float v = accs[co] + bias[co];
        size_t idx = (((size_t)n * 3 + co) * 128 + oh) * 128 + col;
        out[idx] = v;
        float d = v - x[idx];
        lsum = fmaf(d, d, lsum);
    }
    red[tid] = lsum;
    __syncthreads();
    for (int s = 128; s > 0; s >>= 1) {
        if (tid < s) red[tid] += red[tid + s];
        __syncthreads();
    }
    if (tid == 0) rec_part[(size_t)n * 64 + blockIdx.x] = red[0];
}

__global__ void __launch_bounds__(256) finalize_k(const float* __restrict__ rec_part,
                                                  const float* __restrict__ vq_part,
                                                  float* __restrict__ out)
{
    __shared__ double rA[256], rB[256];
    const int tid = threadIdx.x;
    double s = 0.0;
    for (int t = tid; t < 4096; t += 256) s += (double)rec_part[t];
    rA[tid] = s;
    rB[tid] = (double)vq_part[tid];
    __syncthreads();
    for (int st = 128; st > 0; st >>= 1) {
        if (tid < st) { rA[tid] += rA[tid + st]; rB[tid] += rB[tid + st]; }
        __syncthreads();
    }
    if (tid == 0) {
        double recon = rA[0] / 3145728.0;
        double vq    = 1.25 * rB[0] / 4194304.0;
        out[3145728] = (float)(recon + vq);
        out[3145729] = (float)recon;
        out[3145730] = (float)vq;
    }
}

extern "C" void kernel_launch(void* const* d_in, const int* in_sizes, int n_in,
                              void* d_out, int out_size)
{
    (void)in_sizes; (void)n_in; (void)out_size;
    const float* x   = (const float*)d_in[0];
    const float* ew1 = (const float*)d_in[1];
    const float* eb1 = (const float*)d_in[2];
    const float* ew2 = (const float*)d_in[3];
    const float* eb2 = (const float*)d_in[4];
    const float* ew3 = (const float*)d_in[5];
    const float* eb3 = (const float*)d_in[6];
    const float* cb  = (const float*)d_in[7];
    const float* dw1 = (const float*)d_in[8];
    const float* db1 = (const float*)d_in[9];
    const float* dw2 = (const float*)d_in[10];
    const float* db2 = (const float*)d_in[11];
    const float* dw3 = (const float*)d_in[12];
    const float* db3 = (const float*)d_in[13];
    float* out = (float*)d_out;

    void *h1, *h2, *ze, *zq, *dd1, *dd2, *vqp, *recp;
    void *w1t, *w2t, *w3t, *dw1t, *dw2t, *w3dt;
    cudaGetSymbolAddress(&h1,  g_h1);
    cudaGetSymbolAddress(&h2,  g_h2);
    cudaGetSymbolAddress(&ze,  g_ze);
    cudaGetSymbolAddress(&zq,  g_zq);
    cudaGetSymbolAddress(&dd1, g_d1);
    cudaGetSymbolAddress(&dd2, g_d2);
    cudaGetSymbolAddress(&vqp,  g_vq_part);
    cudaGetSymbolAddress(&recp, g_rec_part);
    cudaGetSymbolAddress(&w1t,  g_w1t);
    cudaGetSymbolAddress(&w2t,  g_w2t);
    cudaGetSymbolAddress(&w3t,  g_w3t);
    cudaGetSymbolAddress(&dw1t, g_dw1t);
    cudaGetSymbolAddress(&dw2t, g_dw2t);
    cudaGetSymbolAddress(&w3dt, g_w3dt);

    const int SM_E1 = (1028 + 3 * 64) * 4;
    const int SM_E2 = (128 * 18 * 19 + 64 * 128) * 4;     // 207872
    const int SM_E3 = (128 * 10 * 13 + 128 * 64) * 4;     // 99328
    const int SM_DC = (16 * 10 * 8 + 16 * 16 * 64) * 4;   // 70656
    const int SM_D3 = (8320 + 128 * 9 * 4) * 4;           // 51712
    const int SM_VQ = (32768 + 512) * 4;                  // 133120

    cudaFuncSetAttribute((const void*)enc2_k,
                         cudaFuncAttributeMaxDynamicSharedMemorySize, SM_E2);
    cudaFuncSetAttribute((const void*)enc3_k,
                         cudaFuncAttributeMaxDynamicSharedMemorySize, SM_E3);
    cudaFuncSetAttribute((const void*)deconv_k<64,128,32>,
                         cudaFuncAttributeMaxDynamicSharedMemorySize, SM_DC);
    cudaFuncSetAttribute((const void*)deconv_k<128,128,64>,
                         cudaFuncAttributeMaxDynamicSharedMemorySize, SM_DC);
    cudaFuncSetAttribute((const void*)vq_k,
                         cudaFuncAttributeMaxDynamicSharedMemorySize, SM_VQ);
    cudaFuncSetAttribute((const void*)dec3_k,
                         cudaFuncAttributeMaxDynamicSharedMemorySize, SM_D3);

    wprep_k<<<256, 256>>>(ew1, ew2, ew3, dw1, dw2, dw3);
    conv_seq<4,2,3,128,128,true><<<dim3(64, 2, NB), 512, SM_E1>>>(
        x, (const float*)w1t, eb1, (float*)h1);
    enc2_k<<<dim3(16, 1, NB), 512, SM_E2>>>(
        (const float*)h1, (const float*)w2t, eb2, (float*)h2);
    enc3_k<<<dim3(16, 1, NB), 512, SM_E3>>>(
        (const float*)h2, (const float*)w3t, eb3, (float*)ze);
    vq_k<<<256, 256, SM_VQ>>>(
        (const float*)ze, cb, (float*)zq, (float*)vqp);
    deconv_k<64,128,32><<<dim3(32, 2, NB), 256, SM_DC>>>(
        (const float*)zq, (const float*)dw1t, db1, (float*)dd1);
    deconv_k<128,128,64><<<dim3(128, 2, NB), 256, SM_DC>>>(
        (const float*)dd1, (const float*)dw2t, db2, (float*)dd2);
    dec3_k<<<dim3(64, NB), 256, SM_D3>>>(
        (const float*)dd2, (const float*)w3dt, db3, x, out, (float*)recp);
    finalize_k<<<1, 256>>>(
        (const float*)recp, (const float*)vqp, out);
}

// round 8
// speedup vs baseline: 1.2861x; 1.2861x over previous
#include <cuda_runtime.h>
#include <cstdint>
#include <cstddef>

#define NB 64
typedef unsigned long long ull;

__device__ __forceinline__ ull pack2(float x) {
    ull d; unsigned u = __float_as_uint(x);
    asm("mov.b64 %0, {%1, %1};" : "=l"(d) : "r"(u));
    return d;
}
__device__ __forceinline__ ull fma2(ull a, ull b, ull c) {
    ull d;
    asm("fma.rn.f32x2 %0, %1, %2, %3;" : "=l"(d) : "l"(a), "l"(b), "l"(c));
    return d;
}
__device__ __forceinline__ void unpack2(ull a, float& lo, float& hi) {
    unsigned l, h;
    asm("mov.b64 {%0, %1}, %2;" : "=r"(l), "=r"(h) : "l"(a));
    lo = __uint_as_float(l); hi = __uint_as_float(h);
}

__device__ float g_h1[(size_t)NB * 128 * 64 * 64];
__device__ float g_h2[(size_t)NB * 128 * 32 * 32];
__device__ float g_ze[(size_t)NB * 64 * 32 * 32];
__device__ float g_zq[(size_t)NB * 64 * 32 * 32];
__device__ float g_d1[(size_t)NB * 128 * 64 * 64];
__device__ float g_d2[(size_t)NB * 128 * 128 * 128];
__device__ float g_vq_part[256];
__device__ float g_rec_part[4096];
__device__ float g_w1t[16 * 3 * 128];     // [kk][ci][co]
__device__ float g_w2t[16 * 128 * 128];   // [kk][ci][co]
__device__ float g_w3t[9 * 128 * 64];     // [kk][ci][co]
__device__ float g_dw1t[64 * 16 * 128];   // [ci][kk][co]
__device__ float g_dw2t[128 * 16 * 128];  // [ci][kk][co]
__device__ float g_w3dt[128 * 9 * 3];     // [ci*9+kk][co]

__global__ void wprep_k(const float* __restrict__ w1, const float* __restrict__ w2,
                        const float* __restrict__ w3, const float* __restrict__ dw1,
                        const float* __restrict__ dw2, const float* __restrict__ dw3)
{
    int st = gridDim.x * blockDim.x, g = blockIdx.x * blockDim.x + threadIdx.x;
    for (int t = g; t < 16 * 3 * 128; t += st) {
        int co = t & 127, r = t >> 7, ci = r % 3, kk = r / 3;
        g_w1t[(kk * 3 + ci) * 128 + co] = w1[((size_t)co * 3 + ci) * 16 + kk];
    }
    for (int t = g; t < 16 * 128 * 128; t += st) {
        int co = t & 127, r = t >> 7, ci = r & 127, kk = r >> 7;
        g_w2t[(kk * 128 + ci) * 128 + co] = w2[((size_t)co * 128 + ci) * 16 + kk];
    }
    for (int t = g; t < 9 * 128 * 64; t += st) {
        int co = t & 63, r = t >> 6, ci = r & 127, kk = r >> 7;
        g_w3t[(kk * 128 + ci) * 64 + co] = w3[((size_t)co * 128 + ci) * 9 + kk];
    }
    for (int t = g; t < 64 * 16 * 128; t += st) {
        int co = t & 127, r = t >> 7, kk = r & 15, ci = r >> 4;
        g_dw1t[t] = dw1[((size_t)ci * 128 + co) * 16 + kk];
    }
    for (int t = g; t < 128 * 16 * 128; t += st) {
        int co = t & 127, r = t >> 7, kk = r & 15, ci = r >> 4;
        g_dw2t[t] = dw2[((size_t)ci * 128 + co) * 16 + kk];
    }
    for (int t = g; t < 128 * 9 * 3; t += st) {
        int co = t % 3, r = t / 3, kk = r % 9, ci = r / 9;
        g_w3dt[t] = dw3[((size_t)co * 128 + ci) * 9 + kk];
    }
}

// enc1 (CIN=3): bit-exact scalar chain kernel (unchanged R6).
template <int K, int S, int CIN, int COUT, int H, bool RELU>
__global__ void __launch_bounds__(512) conv_seq(const float* __restrict__ in,
                                                const float* __restrict__ wt,
                                                const float* __restrict__ bias,
                                                float* __restrict__ out)
{
    constexpr int W = H, OH = (H + 2 - K) / S + 1, OW = OH;
    constexpr int IHS = 7 * S + K, IWS = 7 * S + K, IWP = IWS + 1;
    constexpr int SW_OFF = ((CIN * IHS * IWP + 3) / 4) * 4;
    extern __shared__ float sm[];
    float* s_in = sm;
    float* s_w  = sm + SW_OFF;
    const int n = blockIdx.z, co0 = blockIdx.y * 64;
    constexpr int TWn = OW / 8;
    const int oh0 = (blockIdx.x / TWn) * 8, ow0 = (blockIdx.x % TWn) * 8;
    const int tid = threadIdx.x, px = tid & 63, cog = tid >> 6;
    const int ohr = px >> 3, owr = px & 7;
    const int ihb = oh0 * S - 1, iwb = ow0 * S - 1;

    for (int t = tid; t < CIN * IHS * IWS; t += 512) {
        int ci = t / (IHS * IWS), r = t % (IHS * IWS), rr = r / IWS, cc = r % IWS;
        int ih = ihb + rr, iw = iwb + cc;
        float v = 0.f;
        if (ih >= 0 && ih < H && iw >= 0 && iw < W)
            v = in[(((size_t)n * CIN + ci) * H + ih) * W + iw];
        s_in[(ci * IHS + rr) * IWP + cc] = v;
    }
    const int cob = co0 + cog * 8;
    float a[8];
    #pragma unroll
    for (int i = 0; i < 8; i++) a[i] = 0.f;
    #pragma unroll
    for (int kh = 0; kh < K; kh++)
    #pragma unroll
    for (int kw = 0; kw < K; kw++) {
        __syncthreads();
        for (int t = tid; t < CIN * 64; t += 512)
            s_w[t] = wt[(size_t)((kh * K + kw) * CIN + (t >> 6)) * COUT + co0 + (t & 63)];
        __syncthreads();
        const float* ip = &s_in[(ohr * S + kh) * IWP + owr * S + kw];
        const float* wp = &s_w[cog * 8];
        #pragma unroll 3
        for (int ci = 0; ci < CIN; ci++) {
            float iv = ip[ci * IHS * IWP];
            float4 w0 = *(const float4*)&wp[ci * 64];
            float4 w1 = *(const float4*)&wp[ci * 64 + 4];
            a[0] = __fmaf_rn(iv, w0.x, a[0]);
            a[1] = __fmaf_rn(iv, w0.y, a[1]);
            a[2] = __fmaf_rn(iv, w0.z, a[2]);
            a[3] = __fmaf_rn(iv, w0.w, a[3]);
            a[4] = __fmaf_rn(iv, w1.x, a[4]);
            a[5] = __fmaf_rn(iv, w1.y, a[5]);
            a[6] = __fmaf_rn(iv, w1.z, a[6]);
            a[7] = __fmaf_rn(iv, w1.w, a[7]);
        }
    }
    const int oh = oh0 + ohr, ow = ow0 + owr;
    #pragma unroll
    for (int c = 0; c < 8; c++) {
        float v = __fadd_rn(a[c], bias[cob + c]);
        if (RELU) v = fmaxf(v, 0.f);
        out[(((size_t)n * COUT + cob + c) * OH + oh) * OW + ow] = v;
    }
}

// enc2: 128->128 k4s2 relu. f32x2 co-packed (exact R6).
__global__ void __launch_bounds__(512) enc2_k(const float* __restrict__ in,
                                              const float* __restrict__ wt,
                                              const float* __restrict__ bias,
                                              float* __restrict__ out)
{
    extern __shared__ float sm[];
    float* s_in = sm;                 // [128][18][19]
    float* s_w  = sm + 128 * 18 * 19; // [64ci][128co]
    const int n = blockIdx.z;
    const int oh0 = (blockIdx.x >> 2) * 8, ow0 = (blockIdx.x & 3) * 8;
    const int tid = threadIdx.x, px = tid & 31, cog = tid >> 5;
    const int ohr = px >> 2, owp = px & 3;
    const int ihb = oh0 * 2 - 1, iwb = ow0 * 2 - 1;

    for (int t = tid; t < 128 * 18 * 18; t += 512) {
        int ci = t / 324, r = t % 324, rr = r / 18, cc = r % 18;
        int ih = ihb + rr, iw = iwb + cc;
        float v = 0.f;
        if (ih >= 0 && ih < 64 && iw >= 0 && iw < 64)
            v = in[(((size_t)n * 128 + ci) * 64 + ih) * 64 + iw];
        s_in[(ci * 18 + rr) * 19 + cc] = v;
    }

    ull a[2][4];
    #pragma unroll
    for (int p = 0; p < 2; p++)
    #pragma unroll
    for (int j = 0; j < 4; j++) a[p][j] = 0ull;

    #pragma unroll
    for (int kh = 0; kh < 4; kh++)
    #pragma unroll
    for (int kw = 0; kw < 4; kw++) {
        for (int ci0 = 0; ci0 < 128; ci0 += 64) {
            __syncthreads();
            for (int t = tid; t < 64 * 128; t += 512)
                s_w[t] = wt[(size_t)((kh * 4 + kw) * 128 + ci0 + (t >> 7)) * 128 + (t & 127)];
            __syncthreads();
            const float* ip = &s_in[((ci0 * 18) + ohr * 2 + kh) * 19 + owp * 4 + kw];
            const float* wp = &s_w[cog * 8];
            #pragma unroll 2
            for (int ci = 0; ci < 64; ci++) {
                float i0 = ip[ci * 342];
                float i1 = ip[ci * 342 + 2];
                ull p0 = pack2(i0), p1 = pack2(i1);
                ulonglong2 wA = *(const ulonglong2*)&wp[ci * 128];
                ulonglong2 wB = *(const ulonglong2*)&wp[ci * 128 + 4];
                a[0][0] = fma2(p0, wA.x, a[0][0]);
                a[0][1] = fma2(p0, wA.y, a[0][1]);
                a[0][2] = fma2(p0, wB.x, a[0][2]);
                a[0][3] = fma2(p0, wB.y, a[0][3]);
                a[1][0] = fma2(p1, wA.x, a[1][0]);
                a[1][1] = fma2(p1, wA.y, a[1][1]);
                a[1][2] = fma2(p1, wB.x, a[1][2]);
                a[1][3] = fma2(p1, wB.y, a[1][3]);
            }
        }
    }
    const int oh = oh0 + ohr;
    #pragma unroll
    for (int p = 0; p < 2; p++) {
        int ow = ow0 + owp * 2 + p;
        #pragma unroll
        for (int j = 0; j < 4; j++) {
            int co = cog * 8 + 2 * j;
            float lo, hi;
            unpack2(a[p][j], lo, hi);
            out[(((size_t)n * 128 + co) * 32 + oh) * 32 + ow] =
                fmaxf(__fadd_rn(lo, bias[co]), 0.f);
            out[(((size_t)n * 128 + co + 1) * 32 + oh) * 32 + ow] =
                fmaxf(__fadd_rn(hi, bias[co + 1]), 0.f);
        }
    }
}

// enc3: 128->64 k3s1. f32x2, thread = 2px x 8co (exact R6).
__global__ void __launch_bounds__(256) enc3_k(const float* __restrict__ in,
                                              const float* __restrict__ wt,
                                              const float* __restrict__ bias,
                                              float* __restrict__ out)
{
    extern __shared__ float sm[];
    float* s_in = sm;                 // [128][10][11]
    float* s_w  = sm + 128 * 10 * 11; // [128ci][64co]
    const int n = blockIdx.z;
    const int oh0 = (blockIdx.x >> 2) * 8, ow0 = (blockIdx.x & 3) * 8;
    const int tid = threadIdx.x, px = tid & 31, cog = tid >> 5;
    const int ohr = px >> 2, owp = px & 3;
    const int ihb = oh0 - 1, iwb = ow0 - 1;

    for (int t = tid; t < 128 * 10 * 10; t += 256) {
        int ci = t / 100, r = t % 100, rr = r / 10, cc = r % 10;
        int ih = ihb + rr, iw = iwb + cc;
        float v = 0.f;
        if (ih >= 0 && ih < 32 && iw >= 0 && iw < 32)
            v = in[(((size_t)n * 128 + ci) * 32 + ih) * 32 + iw];
        s_in[(ci * 10 + rr) * 11 + cc] = v;
    }

    ull a[2][4];
    #pragma unroll
    for (int p = 0; p < 2; p++)
    #pragma unroll
    for (int j = 0; j < 4; j++) a[p][j] = 0ull;

    #pragma unroll
    for (int kh = 0; kh < 3; kh++)
    #pragma unroll
    for (int kw = 0; kw < 3; kw++) {
        __syncthreads();
        for (int t = tid; t < 128 * 64; t += 256)
            s_w[t] = wt[(size_t)((kh * 3 + kw) * 128 + (t >> 6)) * 64 + (t & 63)];
        __syncthreads();
        const float* ip = &s_in[(ohr + kh) * 11 + owp * 2 + kw];
        const float* wp = &s_w[cog * 8];
        #pragma unroll 2
        for (int ci = 0; ci < 128; ci++) {
            float i0 = ip[ci * 110];
            float i1 = ip[ci * 110 + 1];
            ull p0 = pack2(i0), p1 = pack2(i1);
            ulonglong2 wA = *(const ulonglong2*)&wp[ci * 64];
            ulonglong2 wB = *(const ulonglong2*)&wp[ci * 64 + 4];
            a[0][0] = fma2(p0, wA.x, a[0][0]);
            a[0][1] = fma2(p0, wA.y, a[0][1]);
            a[0][2] = fma2(p0, wB.x, a[0][2]);
            a[0][3] = fma2(p0, wB.y, a[0][3]);
            a[1][0] = fma2(p1, wA.x, a[1][0]);
            a[1][1] = fma2(p1, wA.y, a[1][1]);
            a[1][2] = fma2(p1, wB.x, a[1][2]);
            a[1][3] = fma2(p1, wB.y, a[1][3]);
        }
    }
    const int oh = oh0 + ohr;
    #pragma unroll
    for (int p = 0; p < 2; p++) {
        int ow = ow0 + owp * 2 + p;
        #pragma unroll
        for (int j = 0; j < 4; j++) {
            int co = cog * 8 + 2 * j;
            float lo, hi;
            unpack2(a[p][j], lo, hi);
            out[(((size_t)n * 64 + co) * 32 + oh) * 32 + ow] = __fadd_rn(lo, bias[co]);
            out[(((size_t)n * 64 + co + 1) * 32 + oh) * 32 + ow] = __fadd_rn(hi, bias[co + 1]);
        }
    }
}

// VQ (unchanged bit-exact numerics).
__global__ void __launch_bounds__(256) vq_k(const float* __restrict__ ze,
                                            const float* __restrict__ cb,
                                            float* __restrict__ zq,
                                            float* __restrict__ part)
{
    extern __shared__ float sm[];
    float* s_cb  = sm;
    float* s_cb2 = sm + 32768;
    __shared__ float red[256];
    const int tid = threadIdx.x;
    for (int t = tid; t < 32768; t += 256) s_cb[t] = cb[t];
    __syncthreads();
    for (int k = tid; k < 512; k += 256) {
        float s = 0.f;
        for (int d = 0; d < 64; d++) {
            float c = s_cb[k * 64 + d];
            s = __fadd_rn(s, __fmul_rn(c, c));
        }
        s_cb2[k] = s;
    }
    __syncthreads();

    const int v = blockIdx.x * 256 + tid;
    const int n = v >> 10, hw = v & 1023;
    const float* zp = ze + (size_t)n * 64 * 1024 + hw;
    float z[64];
    #pragma unroll
    for (int d = 0; d < 64; d++) z[d] = zp[(size_t)d * 1024];

    float z2 = 0.f;
    #pragma unroll
    for (int d = 0; d < 64; d++) z2 = __fadd_rn(z2, __fmul_rn(z[d], z[d]));

    float best = 3.4e38f;
    int bi = 0;
    for (int k0 = 0; k0 < 512; k0 += 4) {
        float dt0 = 0.f, dt1 = 0.f, dt2 = 0.f, dt3 = 0.f;
        const float* c0 = &s_cb[(k0 + 0) * 64];
        const float* c1 = &s_cb[(k0 + 1) * 64];
        const float* c2 = &s_cb[(k0 + 2) * 64];
        const float* c3 = &s_cb[(k0 + 3) * 64];
        #pragma unroll
        for (int d = 0; d < 64; d++) {
            float zd = z[d];
            dt0 = __fmaf_rn(zd, c0[d], dt0);
            dt1 = __fmaf_rn(zd, c1[d], dt1);
            dt2 = __fmaf_rn(zd, c2[d], dt2);
            dt3 = __fmaf_rn(zd, c3[d], dt3);
        }
        float s0 = __fsub_rn(__fadd_rn(z2, s_cb2[k0 + 0]), __fmul_rn(2.f, dt0));
        float s1 = __fsub_rn(__fadd_rn(z2, s_cb2[k0 + 1]), __fmul_rn(2.f, dt1));
        float s2 = __fsub_rn(__fadd_rn(z2, s_cb2[k0 + 2]), __fmul_rn(2.f, dt2));
        float s3 = __fsub_rn(__fadd_rn(z2, s_cb2[k0 + 3]), __fmul_rn(2.f, dt3));
        if (s0 < best) { best = s0; bi = k0; }
        if (s1 < best) { best = s1; bi = k0 + 1; }
        if (s2 < best) { best = s2; bi = k0 + 2; }
        if (s3 < best) { best = s3; bi = k0 + 3; }
    }

    float* zqp = zq + (size_t)n * 64 * 1024 + hw;
    float lsum = 0.f;
    #pragma unroll
    for (int d = 0; d < 64; d++) {
        float c = s_cb[bi * 64 + d];
        float df = z[d] - c;
        lsum = fmaf(df, df, lsum);
        zqp[(size_t)d * 1024] = __fadd_rn(z[d], __fsub_rn(c, z[d]));
    }
    red[tid] = lsum;
    __syncthreads();
    for (int s = 128; s > 0; s >>= 1) {
        if (tid < s) red[tid] += red[tid + s];
        __syncthreads();
    }
    if (tid == 0) part[blockIdx.x] = red[0];
}

// ConvTranspose2d k4s2p1 + bias + relu, f32x2 co-packed. wtt: [ci][kk][co].
// Block: 16oh x 64ow x 32co, 512 thr (R6 inner structure, wider tile).
template <int CIN, int COUT, int IH>
__global__ void __launch_bounds__(512) deconv_k(const float* __restrict__ in,
                                                const float* __restrict__ wtt,
                                                const float* __restrict__ bias,
                                                float* __restrict__ out)
{
    constexpr int IW = IH, OH = IH * 2, OW = IW * 2;
    constexpr int OWT = OW / 64;
    constexpr int IWS = 34, IWP = 35;
    extern __shared__ float sm[];
    float* s_in = sm;                   // [16][10][35]
    float* s_w  = sm + 16 * 10 * IWP;   // [16ci*16kk][32co]
    const int n = blockIdx.z, co0 = blockIdx.y * 32;
    const int oh0 = (blockIdx.x / OWT) * 16, ow0 = (blockIdx.x % OWT) * 64;
    const int tid = threadIdx.x;
    const int qc = tid & 15, qr = (tid >> 4) & 7, cog = tid >> 7;
    const int ihb = oh0 / 2 - 1, iwb = ow0 / 2 - 1;

    ull a2[2][4][4];
    #pragma unroll
    for (int i = 0; i < 2; i++)
    #pragma unroll
    for (int j = 0; j < 4; j++)
    #pragma unroll
    for (int c = 0; c < 4; c++) a2[i][j][c] = 0ull;

    for (int ci0 = 0; ci0 < CIN; ci0 += 16) {
        for (int t = tid; t < 16 * 10 * IWS; t += 512) {
            int c = t / (10 * IWS), r = t % (10 * IWS), rr = r / IWS, cc = r % IWS;
            int ih = ihb + rr, iw = iwb + cc;
            float v = 0.f;
            if (ih >= 0 && ih < IH && iw >= 0 && iw < IW)
                v = in[(((size_t)n * CIN + ci0 + c) * IH + ih) * IW + iw];
            s_in[(c * 10 + rr) * IWP + cc] = v;
        }
        for (int t = tid; t < 16 * 16 * 32; t += 512)
            s_w[t] = wtt[(size_t)((ci0 + (t >> 9)) * 16 + ((t >> 5) & 15)) * COUT
                         + co0 + (t & 31)];
        __syncthreads();

        for (int cil = 0; cil < 16; cil++) {
            ull ivd[3][4];
            const float* bp = &s_in[(cil * 10 + qr) * IWP + 2 * qc];
            #pragma unroll
            for (int r = 0; r < 3; r++)
            #pragma unroll
            for (int c = 0; c < 4; c++) ivd[r][c] = pack2(bp[r * IWP + c]);

            #pragma unroll
            for (int kk = 0; kk < 16; kk++) {
                const int kh = kk >> 2, kw = kk & 3;
                const int rr = 2 - ((kh + 1) >> 1);
                const int cb = 2 - ((kw + 1) >> 1);
                const int dh = 1 - (kh & 1);
                const int pw = 1 - (kw & 1);
                const float* wp = &s_w[(cil * 16 + kk) * 32 + cog * 8];
                ulonglong2 uA = *(const ulonglong2*)wp;
                ulonglong2 uB = *(const ulonglong2*)(wp + 4);
                #pragma unroll
                for (int q = 0; q < 2; q++) {
                    ull iv = ivd[rr][cb + q];
                    ull* ap = a2[dh][2 * q + pw];
                    ap[0] = fma2(iv, uA.x, ap[0]);
                    ap[1] = fma2(iv, uA.y, ap[1]);
                    ap[2] = fma2(iv, uB.x, ap[2]);
                    ap[3] = fma2(iv, uB.y, ap[3]);
                }
            }
        }
        __syncthreads();
    }

    #pragma unroll
    for (int dh = 0; dh < 2; dh++) {
        int oh = oh0 + qr * 2 + dh;
        #pragma unroll
        for (int c = 0; c < 4; c++) {
            int co = co0 + cog * 8 + 2 * c;
            float b0 = bias[co], b1 = bias[co + 1];
            float o0[4], o1[4];
            #pragma unroll
            for (int j = 0; j < 4; j++) {
                float lo, hi;
                unpack2(a2[dh][j][c], lo, hi);
                o0[j] = fmaxf(lo + b0, 0.f);
                o1[j] = fmaxf(hi + b1, 0.f);
            }
            float4 v0 = {o0[0], o0[1], o0[2], o0[3]};
            float4 v1 = {o1[0], o1[1], o1[2], o1[3]};
            *(float4*)&out[(((size_t)n * COUT + co) * OH + oh) * OW + ow0 + qc * 4] = v0;
            *(float4*)&out[(((size_t)n * COUT + co + 1) * OH + oh) * OW + ow0 + qc * 4] = v1;
        }
    }
}

// dec3 + recon-MSE partial; float4 weight loads.
__global__ void __launch_bounds__(256) dec3_k(const float* __restrict__ in,
                                              const float* __restrict__ wtt,
                                              const float* __restrict__ bias,
                                              const float* __restrict__ x,
                                              float* __restrict__ out,
                                              float* __restrict__ rec_part)
{
    extern __shared__ float sm[];
    float* s_in = sm;
    float* s_w  = sm + 16 * 4 * 130;
    __shared__ float red[256];
    const int n = blockIdx.y, oh0 = blockIdx.x * 2;
    const int tid = threadIdx.x, r = tid >> 7, col = tid & 127, oh = oh0 + r;

    for (int t = tid; t < 128 * 9 * 3; t += 256)
        s_w[(t / 3) * 4 + t % 3] = wtt[t];

    float a0 = 0.f, a1 = 0.f, a2 = 0.f;
    for (int ci0 = 0; ci0 < 128; ci0 += 16) {
        for (int t = tid; t < 16 * 4 * 130; t += 256) {
            int cil = t / 520, r2 = t % 520, rr = r2 / 130, cc = r2 % 130;
            int ih = oh0 - 1 + rr, iw = cc - 1;
            float v = 0.f;
            if (ih >= 0 && ih < 128 && iw >= 0 && iw < 128)
                v = in[(((size_t)n * 128 + ci0 + cil) * 128 + ih) * 128 + iw];
            s_in[t] = v;
        }
        __syncthreads();
        for (int cil = 0; cil < 16; cil++) {
            #pragma unroll
            for (int kh = 0; kh < 3; kh++) {
                const float* rp = &s_in[(cil * 4 + r + kh) * 130 + col];
                #pragma unroll
                for (int kw = 0; kw < 3; kw++) {
                    float iv = rp[kw];
                    float4 wv = *(const float4*)&s_w[((ci0 + cil) * 9 + kh * 3 + kw) * 4];
                    a0 = fmaf(wv.x, iv, a0);
                    a1 = fmaf(wv.y, iv, a1);
                    a2 = fmaf(wv.z, iv, a2);
                }
            }
        }
        __syncthreads();
    }
    float lsum = 0.f;
    float accs[3] = {a0, a1, a2};
    #pragma unroll
    for (int co = 0; co < 3; co++) {
        float v = accs[co] + bias[co];
        size_t idx = (((size_t)n * 3 + co) * 128 + oh) * 128 + col;
        out[idx] = v;
        float d = v - x[idx];
        lsum = fmaf(d, d, lsum);
    }
    red[tid] = lsum;
    __syncthreads();
    for (int s = 128; s > 0; s >>= 1) {
        if (tid < s) red[tid] += red[tid + s];
        __syncthreads();
    }
    if (tid == 0) rec_part[(size_t)n * 64 + blockIdx.x] = red[0];
}

__global__ void __launch_bounds__(256) finalize_k(const float* __restrict__ rec_part,
                                                  const float* __restrict__ vq_part,
                                                  float* __restrict__ out)
{
    __shared__ double rA[256], rB[256];
    const int tid = threadIdx.x;
    double s = 0.0;
    for (int t = tid; t < 4096; t += 256) s += (double)rec_part[t];
    rA[tid] = s;
    rB[tid] = (double)vq_part[tid];
    __syncthreads();
    for (int st = 128; st > 0; st >>= 1) {
        if (tid < st) { rA[tid] += rA[tid + st]; rB[tid] += rB[tid + st]; }
        __syncthreads();
    }
    if (tid == 0) {
        double recon = rA[0] / 3145728.0;
        double vq    = 1.25 * rB[0] / 4194304.0;
        out[3145728] = (float)(recon + vq);
        out[3145729] = (float)recon;
        out[3145730] = (float)vq;
    }
}

extern "C" void kernel_launch(void* const* d_in, const int* in_sizes, int n_in,
                              void* d_out, int out_size)
{
    (void)in_sizes; (void)n_in; (void)out_size;
    const float* x   = (const float*)d_in[0];
    const float* ew1 = (const float*)d_in[1];
    const float* eb1 = (const float*)d_in[2];
    const float* ew2 = (const float*)d_in[3];
    const float* eb2 = (const float*)d_in[4];
    const float* ew3 = (const float*)d_in[5];
    const float* eb3 = (const float*)d_in[6];
    const float* cb  = (const float*)d_in[7];
    const float* dw1 = (const float*)d_in[8];
    const float* db1 = (const float*)d_in[9];
    const float* dw2 = (const float*)d_in[10];
    const float* db2 = (const float*)d_in[11];
    const float* dw3 = (const float*)d_in[12];
    const float* db3 = (const float*)d_in[13];
    float* out = (float*)d_out;

    void *h1, *h2, *ze, *zq, *dd1, *dd2, *vqp, *recp;
    void *w1t, *w2t, *w3t, *dw1t, *dw2t, *w3dt;
    cudaGetSymbolAddress(&h1,  g_h1);
    cudaGetSymbolAddress(&h2,  g_h2);
    cudaGetSymbolAddress(&ze,  g_ze);
    cudaGetSymbolAddress(&zq,  g_zq);
    cudaGetSymbolAddress(&dd1, g_d1);
    cudaGetSymbolAddress(&dd2, g_d2);
    cudaGetSymbolAddress(&vqp,  g_vq_part);
    cudaGetSymbolAddress(&recp, g_rec_part);
    cudaGetSymbolAddress(&w1t,  g_w1t);
    cudaGetSymbolAddress(&w2t,  g_w2t);
    cudaGetSymbolAddress(&w3t,  g_w3t);
    cudaGetSymbolAddress(&dw1t, g_dw1t);
    cudaGetSymbolAddress(&dw2t, g_dw2t);
    cudaGetSymbolAddress(&w3dt, g_w3dt);

    const int SM_E1 = (1028 + 3 * 64) * 4;
    const int SM_E2 = (128 * 18 * 19 + 64 * 128) * 4;       // 207872
    const int SM_E3 = (128 * 10 * 11 + 128 * 64) * 4;       // 89088
    const int SM_DC = (16 * 10 * 35 + 16 * 16 * 32) * 4;    // 55168
    const int SM_D3 = (8320 + 128 * 9 * 4) * 4;             // 51712
    const int SM_VQ = (32768 + 512) * 4;                    // 133120

    cudaFuncSetAttribute((const void*)enc2_k,
                         cudaFuncAttributeMaxDynamicSharedMemorySize, SM_E2);
    cudaFuncSetAttribute((const void*)enc3_k,
                         cudaFuncAttributeMaxDynamicSharedMemorySize, SM_E3);
    cudaFuncSetAttribute((const void*)deconv_k<64,128,32>,
                         cudaFuncAttributeMaxDynamicSharedMemorySize, SM_DC);
    cudaFuncSetAttribute((const void*)deconv_k<128,128,64>,
                         cudaFuncAttributeMaxDynamicSharedMemorySize, SM_DC);
    cudaFuncSetAttribute((const void*)vq_k,
                         cudaFuncAttributeMaxDynamicSharedMemorySize, SM_VQ);
    cudaFuncSetAttribute((const void*)dec3_k,
                         cudaFuncAttributeMaxDynamicSharedMemorySize, SM_D3);

    wprep_k<<<256, 256>>>(ew1, ew2, ew3, dw1, dw2, dw3);
    conv_seq<4,2,3,128,128,true><<<dim3(64, 2, NB), 512, SM_E1>>>(
        x, (const float*)w1t, eb1, (float*)h1);
    enc2_k<<<dim3(16, 1, NB), 512, SM_E2>>>(
        (const float*)h1, (const float*)w2t, eb2, (float*)h2);
    enc3_k<<<dim3(16, 1, NB), 256, SM_E3>>>(
        (const float*)h2, (const float*)w3t, eb3, (float*)ze);
    vq_k<<<256, 256, SM_VQ>>>(
        (const float*)ze, cb, (float*)zq, (float*)vqp);
    deconv_k<64,128,32><<<dim3(4, 4, NB), 512, SM_DC>>>(
        (const float*)zq, (const float*)dw1t, db1, (float*)dd1);
    deconv_k<128,128,64><<<dim3(16, 4, NB), 512, SM_DC>>>(
        (const float*)dd1, (const float*)dw2t, db2, (float*)dd2);
    dec3_k<<<dim3(64, NB), 256, SM_D3>>>(
        (const float*)dd2, (const float*)w3dt, db3, x, out, (float*)recp);
    finalize_k<<<1, 256>>>(
        (const float*)recp, (const float*)vqp, out);
}

// round 10
// speedup vs baseline: 1.5643x; 1.2163x over previous
#include <cuda_runtime.h>
#include <cuda_bf16.h>
#include <cstdint>
#include <cstddef>

#define NB 64
typedef unsigned long long ull;
typedef unsigned int uint32;

__device__ __forceinline__ ull pack2(float x) {
    ull d; unsigned u = __float_as_uint(x);
    asm("mov.b64 %0, {%1, %1};" : "=l"(d) : "r"(u));
    return d;
}
__device__ __forceinline__ ull fma2(ull a, ull b, ull c) {
    ull d;
    asm("fma.rn.f32x2 %0, %1, %2, %3;" : "=l"(d) : "l"(a), "l"(b), "l"(c));
    return d;
}
__device__ __forceinline__ void unpack2(ull a, float& lo, float& hi) {
    unsigned l, h;
    asm("mov.b64 {%0, %1}, %2;" : "=r"(l), "=r"(h) : "l"(a));
    lo = __uint_as_float(l); hi = __uint_as_float(h);
}
__device__ __forceinline__ uint32 smem_u32(const void* p) {
    uint32 a;
    asm("{ .reg .u64 t; cvta.to.shared.u64 t, %1; cvt.u32.u64 %0, t; }" : "=r"(a) : "l"(p));
    return a;
}
__device__ __forceinline__ void ldm_x4(uint32& r0, uint32& r1, uint32& r2, uint32& r3, uint32 a) {
    asm volatile("ldmatrix.sync.aligned.m8n8.x4.shared.b16 {%0,%1,%2,%3}, [%4];"
                 : "=r"(r0), "=r"(r1), "=r"(r2), "=r"(r3) : "r"(a));
}
__device__ __forceinline__ void ldm_x2(uint32& r0, uint32& r1, uint32 a) {
    asm volatile("ldmatrix.sync.aligned.m8n8.x2.shared.b16 {%0,%1}, [%2];"
                 : "=r"(r0), "=r"(r1) : "r"(a));
}
__device__ __forceinline__ void mma16816(float* c, const uint32* a, const uint32* b) {
    asm volatile(
        "mma.sync.aligned.m16n8k16.row.col.f32.bf16.bf16.f32 "
        "{%0,%1,%2,%3}, {%4,%5,%6,%7}, {%8,%9}, {%0,%1,%2,%3};"
        : "+f"(c[0]), "+f"(c[1]), "+f"(c[2]), "+f"(c[3])
        : "r"(a[0]), "r"(a[1]), "r"(a[2]), "r"(a[3]), "r"(b[0]), "r"(b[1]));
}
__device__ __forceinline__ uint32 pkbf2(float a, float b) {
    return (uint32)__bfloat16_as_ushort(__float2bfloat16(a))
         | ((uint32)__bfloat16_as_ushort(__float2bfloat16(b)) << 16);
}
__device__ __forceinline__ float bfres(float v) {
    return v - __bfloat162float(__float2bfloat16(v));
}

__device__ float g_h1[(size_t)NB * 128 * 64 * 64];
__device__ float g_h2[(size_t)NB * 128 * 32 * 32];
__device__ float g_ze[(size_t)NB * 64 * 32 * 32];
__device__ float g_zq[(size_t)NB * 64 * 32 * 32];
__device__ float g_d1[(size_t)NB * 128 * 64 * 64];
__device__ float g_d2[(size_t)NB * 128 * 128 * 128];
__device__ float g_vq_part[256];
__device__ float g_rec_part[4096];
__device__ float g_w1t[16 * 3 * 128];
__device__ float g_w2t[16 * 128 * 128];
__device__ float g_w3t[9 * 128 * 64];
__device__ float g_w3dt[128 * 9 * 3];
__device__ __align__(16) __nv_bfloat16 g_bw1[4 * 2 * 128 * 256];  // [cl][h][co][K]
__device__ __align__(16) __nv_bfloat16 g_bw2[4 * 2 * 128 * 512];  // [cl][h][co][K]

__global__ void wprep_k(const float* __restrict__ w1, const float* __restrict__ w2,
                        const float* __restrict__ w3, const float* __restrict__ dw1,
                        const float* __restrict__ dw2, const float* __restrict__ dw3)
{
    int st = gridDim.x * blockDim.x, g = blockIdx.x * blockDim.x + threadIdx.x;
    for (int t = g; t < 16 * 3 * 128; t += st) {
        int co = t & 127, r = t >> 7, ci = r % 3, kk = r / 3;
        g_w1t[(kk * 3 + ci) * 128 + co] = w1[((size_t)co * 3 + ci) * 16 + kk];
    }
    for (int t = g; t < 16 * 128 * 128; t += st) {
        int co = t & 127, r = t >> 7, ci = r & 127, kk = r >> 7;
        g_w2t[(kk * 128 + ci) * 128 + co] = w2[((size_t)co * 128 + ci) * 16 + kk];
    }
    for (int t = g; t < 9 * 128 * 64; t += st) {
        int co = t & 63, r = t >> 6, ci = r & 127, kk = r >> 7;
        g_w3t[(kk * 128 + ci) * 64 + co] = w3[((size_t)co * 128 + ci) * 9 + kk];
    }
    for (int t = g; t < 128 * 9 * 3; t += st) {
        int co = t % 3, r = t / 3, kk = r % 9, ci = r / 9;
        g_w3dt[t] = dw3[((size_t)co * 128 + ci) * 9 + kk];
    }
    // B[cl][h][co][k], k = ci*4 + rr*2 + cc, w tap = [1-dh+2rr][1-dw+2cc]
    for (int t = g; t < 4 * 2 * 128 * 256; t += st) {
        int k = t & 255, r2 = t >> 8, co = r2 & 127, h = (r2 >> 7) & 1, cl = r2 >> 8;
        int ci = k >> 2, rr = (k >> 1) & 1, cc = k & 1;
        int dh = cl >> 1, dw = cl & 1;
        float w = dw1[((size_t)ci * 128 + co) * 16 + (1 - dh + 2 * rr) * 4 + (1 - dw + 2 * cc)];
        g_bw1[t] = __float2bfloat16(h ? bfres(w) : w);
    }
    for (int t = g; t < 4 * 2 * 128 * 512; t += st) {
        int k = t & 511, r2 = t >> 9, co = r2 & 127, h = (r2 >> 7) & 1, cl = r2 >> 8;
        int ci = k >> 2, rr = (k >> 1) & 1, cc = k & 1;
        int dh = cl >> 1, dw = cl & 1;
        float w = dw2[((size_t)ci * 128 + co) * 16 + (1 - dh + 2 * rr) * 4 + (1 - dw + 2 * cc)];
        g_bw2[t] = __float2bfloat16(h ? bfres(w) : w);
    }
}

// enc1 (bit-exact scalar chain).
template <int K, int S, int CIN, int COUT, int H, bool RELU>
__global__ void __launch_bounds__(512) conv_seq(const float* __restrict__ in,
                                                const float* __restrict__ wt,
                                                const float* __restrict__ bias,
                                                float* __restrict__ out)
{
    constexpr int W = H, OH = (H + 2 - K) / S + 1, OW = OH;
    constexpr int IHS = 7 * S + K, IWS = 7 * S + K, IWP = IWS + 1;
    constexpr int SW_OFF = ((CIN * IHS * IWP + 3) / 4) * 4;
    extern __shared__ float sm[];
    float* s_in = sm;
    float* s_w  = sm + SW_OFF;
    const int n = blockIdx.z, co0 = blockIdx.y * 64;
    constexpr int TWn = OW / 8;
    const int oh0 = (blockIdx.x / TWn) * 8, ow0 = (blockIdx.x % TWn) * 8;
    const int tid = threadIdx.x, px = tid & 63, cog = tid >> 6;
    const int ohr = px >> 3, owr = px & 7;
    const int ihb = oh0 * S - 1, iwb = ow0 * S - 1;

    for (int t = tid; t < CIN * IHS * IWS; t += 512) {
        int ci = t / (IHS * IWS), r = t % (IHS * IWS), rr = r / IWS, cc = r % IWS;
        int ih = ihb + rr, iw = iwb + cc;
        float v = 0.f;
        if (ih >= 0 && ih < H && iw >= 0 && iw < W)
            v = in[(((size_t)n * CIN + ci) * H + ih) * W + iw];
        s_in[(ci * IHS + rr) * IWP + cc] = v;
    }
    const int cob = co0 + cog * 8;
    float a[8];
    #pragma unroll
    for (int i = 0; i < 8; i++) a[i] = 0.f;
    #pragma unroll
    for (int kh = 0; kh < K; kh++)
    #pragma unroll
    for (int kw = 0; kw < K; kw++) {
        __syncthreads();
        for (int t = tid; t < CIN * 64; t += 512)
            s_w[t] = wt[(size_t)((kh * K + kw) * CIN + (t >> 6)) * COUT + co0 + (t & 63)];
        __syncthreads();
        const float* ip = &s_in[(ohr * S + kh) * IWP + owr * S + kw];
        const float* wp = &s_w[cog * 8];
        #pragma unroll 3
        for (int ci = 0; ci < CIN; ci++) {
            float iv = ip[ci * IHS * IWP];
            float4 w0 = *(const float4*)&wp[ci * 64];
            float4 w1 = *(const float4*)&wp[ci * 64 + 4];
            a[0] = __fmaf_rn(iv, w0.x, a[0]);
            a[1] = __fmaf_rn(iv, w0.y, a[1]);
            a[2] = __fmaf_rn(iv, w0.z, a[2]);
            a[3] = __fmaf_rn(iv, w0.w, a[3]);
            a[4] = __fmaf_rn(iv, w1.x, a[4]);
            a[5] = __fmaf_rn(iv, w1.y, a[5]);
            a[6] = __fmaf_rn(iv, w1.z, a[6]);
            a[7] = __fmaf_rn(iv, w1.w, a[7]);
        }
    }
    const int oh = oh0 + ohr, ow = ow0 + owr;
    #pragma unroll
    for (int c = 0; c < 8; c++) {
        float v = __fadd_rn(a[c], bias[cob + c]);
        if (RELU) v = fmaxf(v, 0.f);
        out[(((size_t)n * COUT + cob + c) * OH + oh) * OW + ow] = v;
    }
}

// enc2 (unchanged R6).
__global__ void __launch_bounds__(512) enc2_k(const float* __restrict__ in,
                                              const float* __restrict__ wt,
                                              const float* __restrict__ bias,
                                              float* __restrict__ out)
{
    extern __shared__ float sm[];
    float* s_in = sm;
    float* s_w  = sm + 128 * 18 * 19;
    const int n = blockIdx.z;
    const int oh0 = (blockIdx.x >> 2) * 8, ow0 = (blockIdx.x & 3) * 8;
    const int tid = threadIdx.x, px = tid & 31, cog = tid >> 5;
    const int ohr = px >> 2, owp = px & 3;
    const int ihb = oh0 * 2 - 1, iwb = ow0 * 2 - 1;

    for (int t = tid; t < 128 * 18 * 18; t += 512) {
        int ci = t / 324, r = t % 324, rr = r / 18, cc = r % 18;
        int ih = ihb + rr, iw = iwb + cc;
        float v = 0.f;
        if (ih >= 0 && ih < 64 && iw >= 0 && iw < 64)
            v = in[(((size_t)n * 128 + ci) * 64 + ih) * 64 + iw];
        s_in[(ci * 18 + rr) * 19 + cc] = v;
    }

    ull a[2][4];
    #pragma unroll
    for (int p = 0; p < 2; p++)
    #pragma unroll
    for (int j = 0; j < 4; j++) a[p][j] = 0ull;

    #pragma unroll
    for (int kh = 0; kh < 4; kh++)
    #pragma unroll
    for (int kw = 0; kw < 4; kw++) {
        for (int ci0 = 0; ci0 < 128; ci0 += 64) {
            __syncthreads();
            for (int t = tid; t < 64 * 128; t += 512)
                s_w[t] = wt[(size_t)((kh * 4 + kw) * 128 + ci0 + (t >> 7)) * 128 + (t & 127)];
            __syncthreads();
            const float* ip = &s_in[((ci0 * 18) + ohr * 2 + kh) * 19 + owp * 4 + kw];
            const float* wp = &s_w[cog * 8];
            #pragma unroll 2
            for (int ci = 0; ci < 64; ci++) {
                float i0 = ip[ci * 342];
                float i1 = ip[ci * 342 + 2];
                ull p0 = pack2(i0), p1 = pack2(i1);
                ulonglong2 wA = *(const ulonglong2*)&wp[ci * 128];
                ulonglong2 wB = *(const ulonglong2*)&wp[ci * 128 + 4];
                a[0][0] = fma2(p0, wA.x, a[0][0]);
                a[0][1] = fma2(p0, wA.y, a[0][1]);
                a[0][2] = fma2(p0, wB.x, a[0][2]);
                a[0][3] = fma2(p0, wB.y, a[0][3]);
                a[1][0] = fma2(p1, wA.x, a[1][0]);
                a[1][1] = fma2(p1, wA.y, a[1][1]);
                a[1][2] = fma2(p1, wB.x, a[1][2]);
                a[1][3] = fma2(p1, wB.y, a[1][3]);
            }
        }
    }
    const int oh = oh0 + ohr;
    #pragma unroll
    for (int p = 0; p < 2; p++) {
        int ow = ow0 + owp * 2 + p;
        #pragma unroll
        for (int j = 0; j < 4; j++) {
            int co = cog * 8 + 2 * j;
            float lo, hi;
            unpack2(a[p][j], lo, hi);
            out[(((size_t)n * 128 + co) * 32 + oh) * 32 + ow] =
                fmaxf(__fadd_rn(lo, bias[co]), 0.f);
            out[(((size_t)n * 128 + co + 1) * 32 + oh) * 32 + ow] =
                fmaxf(__fadd_rn(hi, bias[co + 1]), 0.f);
        }
    }
}

// enc3 (unchanged R6).
__global__ void __launch_bounds__(256) enc3_k(const float* __restrict__ in,
                                              const float* __restrict__ wt,
                                              const float* __restrict__ bias,
                                              float* __restrict__ out)
{
    extern __shared__ float sm[];
    float* s_in = sm;
    float* s_w  = sm + 128 * 10 * 11;
    const int n = blockIdx.z;
    const int oh0 = (blockIdx.x >> 2) * 8, ow0 = (blockIdx.x & 3) * 8;
    const int tid = threadIdx.x, px = tid & 31, cog = tid >> 5;
    const int ohr = px >> 2, owp = px & 3;
    const int ihb = oh0 - 1, iwb = ow0 - 1;

    for (int t = tid; t < 128 * 10 * 10; t += 256) {
        int ci = t / 100, r = t % 100, rr = r / 10, cc = r % 10;
        int ih = ihb + rr, iw = iwb + cc;
        float v = 0.f;
        if (ih >= 0 && ih < 32 && iw >= 0 && iw < 32)
            v = in[(((size_t)n * 128 + ci) * 32 + ih) * 32 + iw];
        s_in[(ci * 10 + rr) * 11 + cc] = v;
    }

    ull a[2][4];
    #pragma unroll
    for (int p = 0; p < 2; p++)
    #pragma unroll
    for (int j = 0; j < 4; j++) a[p][j] = 0ull;

    #pragma unroll
    for (int kh = 0; kh < 3; kh++)
    #pragma unroll
    for (int kw = 0; kw < 3; kw++) {
        __syncthreads();
        for (int t = tid; t < 128 * 64; t += 256)
            s_w[t] = wt[(size_t)((kh * 3 + kw) * 128 + (t >> 6)) * 64 + (t & 63)];
        __syncthreads();
        const float* ip = &s_in[(ohr + kh) * 11 + owp * 2 + kw];
        const float* wp = &s_w[cog * 8];
        #pragma unroll 2
        for (int ci = 0; ci < 128; ci++) {
            float i0 = ip[ci * 110];
            float i1 = ip[ci * 110 + 1];
            ull p0 = pack2(i0), p1 = pack2(i1);
            ulonglong2 wA = *(const ulonglong2*)&wp[ci * 64];
            ulonglong2 wB = *(const ulonglong2*)&wp[ci * 64 + 4];
            a[0][0] = fma2(p0, wA.x, a[0][0]);
            a[0][1] = fma2(p0, wA.y, a[0][1]);
            a[0][2] = fma2(p0, wB.x, a[0][2]);
            a[0][3] = fma2(p0, wB.y, a[0][3]);
            a[1][0] = fma2(p1, wA.x, a[1][0]);
            a[1][1] = fma2(p1, wA.y, a[1][1]);
            a[1][2] = fma2(p1, wB.x, a[1][2]);
            a[1][3] = fma2(p1, wB.y, a[1][3]);
        }
    }
    const int oh = oh0 + ohr;
    #pragma unroll
    for (int p = 0; p < 2; p++) {
        int ow = ow0 + owp * 2 + p;
        #pragma unroll
        for (int j = 0; j < 4; j++) {
            int co = cog * 8 + 2 * j;
            float lo, hi;
            unpack2(a[p][j], lo, hi);
            out[(((size_t)n * 64 + co) * 32 + oh) * 32 + ow] = __fadd_rn(lo, bias[co]);
            out[(((size_t)n * 64 + co + 1) * 32 + oh) * 32 + ow] = __fadd_rn(hi, bias[co + 1]);
        }
    }
}

// VQ (unchanged bit-exact numerics).
__global__ void __launch_bounds__(256) vq_k(const float* __restrict__ ze,
                                            const float* __restrict__ cb,
                                            float* __restrict__ zq,
                                            float* __restrict__ part)
{
    extern __shared__ float sm[];
    float* s_cb  = sm;
    float* s_cb2 = sm + 32768;
    __shared__ float red[256];
    const int tid = threadIdx.x;
    for (int t = tid; t < 32768; t += 256) s_cb[t] = cb[t];
    __syncthreads();
    for (int k = tid; k < 512; k += 256) {
        float s = 0.f;
        for (int d = 0; d < 64; d++) {
            float c = s_cb[k * 64 + d];
            s = __fadd_rn(s, __fmul_rn(c, c));
        }
        s_cb2[k] = s;
    }
    __syncthreads();

    const int v = blockIdx.x * 256 + tid;
    const int n = v >> 10, hw = v & 1023;
    const float* zp = ze + (size_t)n * 64 * 1024 + hw;
    float z[64];
    #pragma unroll
    for (int d = 0; d < 64; d++) z[d] = zp[(size_t)d * 1024];

    float z2 = 0.f;
    #pragma unroll
    for (int d = 0; d < 64; d++) z2 = __fadd_rn(z2, __fmul_rn(z[d], z[d]));

    float best = 3.4e38f;
    int bi = 0;
    for (int k0 = 0; k0 < 512; k0 += 4) {
        float dt0 = 0.f, dt1 = 0.f, dt2 = 0.f, dt3 = 0.f;
        const float* c0 = &s_cb[(k0 + 0) * 64];
        const float* c1 = &s_cb[(k0 + 1) * 64];
        const float* c2 = &s_cb[(k0 + 2) * 64];
        const float* c3 = &s_cb[(k0 + 3) * 64];
        #pragma unroll
        for (int d = 0; d < 64; d++) {
            float zd = z[d];
            dt0 = __fmaf_rn(zd, c0[d], dt0);
            dt1 = __fmaf_rn(zd, c1[d], dt1);
            dt2 = __fmaf_rn(zd, c2[d], dt2);
            dt3 = __fmaf_rn(zd, c3[d], dt3);
        }
        float s0 = __fsub_rn(__fadd_rn(z2, s_cb2[k0 + 0]), __fmul_rn(2.f, dt0));
        float s1 = __fsub_rn(__fadd_rn(z2, s_cb2[k0 + 1]), __fmul_rn(2.f, dt1));
        float s2 = __fsub_rn(__fadd_rn(z2, s_cb2[k0 + 2]), __fmul_rn(2.f, dt2));
        float s3 = __fsub_rn(__fadd_rn(z2, s_cb2[k0 + 3]), __fmul_rn(2.f, dt3));
        if (s0 < best) { best = s0; bi = k0; }
        if (s1 < best) { best = s1; bi = k0 + 1; }
        if (s2 < best) { best = s2; bi = k0 + 2; }
        if (s3 < best) { best = s3; bi = k0 + 3; }
    }

    float* zqp = zq + (size_t)n * 64 * 1024 + hw;
    float lsum = 0.f;
    #pragma unroll
    for (int d = 0; d < 64; d++) {
        float c = s_cb[bi * 64 + d];
        float df = z[d] - c;
        lsum = fmaf(df, df, lsum);
        zqp[(size_t)d * 1024] = __fadd_rn(z[d], __fsub_rn(c, z[d]));
    }
    red[tid] = lsum;
    __syncthreads();
    for (int s = 128; s > 0; s >>= 1) {
        if (tid < s) red[tid] += red[tid + s];
        __syncthreads();
    }
    if (tid == 0) part[blockIdx.x] = red[0];
}

// ---------------------------------------------------------------------------
// Deconv via mma.sync bf16 (baseline PTX): per parity class,
// D[128px, 128co] = A[128px,K] * B[128co,K]^T, split-bf16 3-product.
// Block 256 thr = 8 warps; warp tile 32px x 64co. K-chunks of 64.
// ---------------------------------------------------------------------------
template <int CIN, int IHW>
__global__ void __launch_bounds__(256) deconv_mma_k(
    const float* __restrict__ in, const __nv_bfloat16* __restrict__ gB,
    const float* __restrict__ bias, float* __restrict__ out)
{
    constexpr int K = CIN * 4;
    constexpr int NCH = K / 64;
    constexpr int OH = IHW * 2, OW = IHW * 2;
    constexpr int TX = IHW / 16;
    constexpr int PATCH_B = CIN * 180 * 4;
    constexpr int AH_B = PATCH_B, AL_B = AH_B + 18432;
    constexpr int BH_B = AL_B + 18432, BL_B = BH_B + 18432;

    extern __shared__ char smc[];
    float* s_patch = (float*)smc;
    const uint32 sb = smem_u32(smc);

    const int tid = threadIdx.x;
    const int lane = tid & 31, wrp = tid >> 5;
    const int mg = wrp & 3, ng = wrp >> 2;
    const int n = blockIdx.z, cl = blockIdx.y;
    const int dh = cl >> 1, dw = cl & 1;
    const int y0 = (blockIdx.x / TX) * 8, x0 = (blockIdx.x % TX) * 16;

    // stage fp32 input patch [CIN][10][18]
    for (int t = tid; t < CIN * 180; t += 256) {
        int ci = t / 180, r = t % 180, rr = r / 18, cc = r % 18;
        int yy = y0 - 1 + rr, xx = x0 - 1 + cc;
        float v = 0.f;
        if (yy >= 0 && yy < IHW && xx >= 0 && xx < IHW)
            v = in[(((size_t)n * CIN + ci) * IHW + yy) * IHW + xx];
        s_patch[t] = v;
    }

    float c[2][8][4];
    #pragma unroll
    for (int i = 0; i < 2; i++)
    #pragma unroll
    for (int j = 0; j < 8; j++)
    #pragma unroll
    for (int q = 0; q < 4; q++) c[i][j][q] = 0.f;

    const int am = tid >> 1, aks = (tid & 1) * 32;
    const int a_yl = am >> 4, a_xl = am & 15;
    const int a_pr0 = a_yl + dh + 1, a_pc0 = a_xl + dw + 1;

    for (int kc = 0; kc < NCH; kc++) {
        __syncthreads();
        // build A hi/lo chunk [128][64] bf16 (row stride 72 halves)
        {
            uint32* ah = (uint32*)(smc + AH_B);
            uint32* al = (uint32*)(smc + AL_B);
            const int kc16 = kc * 16;
            #pragma unroll 4
            for (int j2 = 0; j2 < 16; j2++) {
                int k = aks + 2 * j2;
                int ci = kc16 + (k >> 2);
                int r = (k >> 1) & 1;
                const float* pp = &s_patch[(ci * 10 + (a_pr0 - r)) * 18];
                float v0 = pp[a_pc0];
                float v1 = pp[a_pc0 - 1];
                int idx = (am * 72 + k) >> 1;
                ah[idx] = pkbf2(v0, v1);
                al[idx] = pkbf2(bfres(v0), bfres(v1));
            }
        }
        // stage B hi/lo chunk [128co][64k]
        {
            const __nv_bfloat16* bh = gB + ((size_t)(cl * 2 + 0) * 128) * K + kc * 64;
            const __nv_bfloat16* bl = gB + ((size_t)(cl * 2 + 1) * 128) * K + kc * 64;
            for (int e = tid; e < 1024; e += 256) {
                int co = e >> 3, k8 = (e & 7) * 8;
                uint4 vh = *(const uint4*)(bh + (size_t)co * K + k8);
                uint4 vl = *(const uint4*)(bl + (size_t)co * K + k8);
                *(uint4*)(smc + BH_B + (co * 72 + k8) * 2) = vh;
                *(uint4*)(smc + BL_B + (co * 72 + k8) * 2) = vl;
            }
        }
        __syncthreads();

        #pragma unroll
        for (int k16i = 0; k16i < 4; k16i++) {
            const int k16 = k16i * 16;
            uint32 a_h[2][4], a_l[2][4];
            #pragma unroll
            for (int i = 0; i < 2; i++) {
                int row = mg * 32 + i * 16 + (lane & 15);
                uint32 off = (uint32)((row * 72 + k16 + ((lane >> 4) << 3)) * 2);
                ldm_x4(a_h[i][0], a_h[i][1], a_h[i][2], a_h[i][3], sb + AH_B + off);
                ldm_x4(a_l[i][0], a_l[i][1], a_l[i][2], a_l[i][3], sb + AL_B + off);
            }
            uint32 b_h[8][2], b_l[8][2];
            #pragma unroll
            for (int j = 0; j < 8; j++) {
                int nrow = ng * 64 + j * 8 + (lane & 7);
                uint32 off = (uint32)((nrow * 72 + k16 + (((lane >> 3) & 1) << 3)) * 2);
                ldm_x2(b_h[j][0], b_h[j][1], sb + BH_B + off);
                ldm_x2(b_l[j][0], b_l[j][1], sb + BL_B + off);
            }
            #pragma unroll
            for (int i = 0; i < 2; i++)
            #pragma unroll
            for (int j = 0; j < 8; j++) {
                mma16816(c[i][j], a_h[i], b_h[j]);
                mma16816(c[i][j], a_h[i], b_l[j]);
                mma16816(c[i][j], a_l[i], b_h[j]);
            }
        }
    }

    // write out: row -> pixel, col -> co
    #pragma unroll
    for (int i = 0; i < 2; i++) {
        int row0 = mg * 32 + i * 16 + (lane >> 2);
        #pragma unroll
        for (int rr = 0; rr < 2; rr++) {
            int row = row0 + rr * 8;
            int y_l = row >> 4, x_l = row & 15;
            int oh = 2 * (y0 + y_l) + dh, ow = 2 * (x0 + x_l) + dw;
            size_t ob = ((size_t)n * 128) * OH * OW + (size_t)oh * OW + ow;
            #pragma unroll
            for (int j = 0; j < 8; j++) {
                int col = ng * 64 + j * 8 + (lane & 3) * 2;
                float v0 = c[i][j][rr * 2 + 0] + bias[col];
                float v1 = c[i][j][rr * 2 + 1] + bias[col + 1];
                out[ob + (size_t)col * OH * OW] = fmaxf(v0, 0.f);
                out[ob + (size_t)(col + 1) * OH * OW] = fmaxf(v1, 0.f);
            }
        }
    }
}

// dec3 + recon-MSE partial.
__global__ void __launch_bounds__(256) dec3_k(const float* __restrict__ in,
                                              const float* __restrict__ wtt,
                                              const float* __restrict__ bias,
                                              const float* __restrict__ x,
                                              float* __restrict__ out,
                                              float* __restrict__ rec_part)
{
    extern __shared__ float sm[];
    float* s_in = sm;
    float* s_w  = sm + 16 * 4 * 130;
    __shared__ float red[256];
    const int n = blockIdx.y, oh0 = blockIdx.x * 2;
    const int tid = threadIdx.x, r = tid >> 7, col = tid & 127, oh = oh0 + r;

    for (int t = tid; t < 128 * 9 * 3; t += 256)
        s_w[(t / 3) * 4 + t % 3] = wtt[t];

    float a0 = 0.f, a1 = 0.f, a2 = 0.f;
    for (int ci0 = 0; ci0 < 128; ci0 += 16) {
        for (int t = tid; t < 16 * 4 * 130; t += 256) {
            int cil = t / 520, r2 = t % 520, rr = r2 / 130, cc = r2 % 130;
            int ih = oh0 - 1 + rr, iw = cc - 1;
            float v = 0.f;
            if (ih >= 0 && ih < 128 && iw >= 0 && iw < 128)
                v = in[(((size_t)n * 128 + ci0 + cil) * 128 + ih) * 128 + iw];
            s_in[t] = v;
        }
        __syncthreads();
        for (int cil = 0; cil < 16; cil++) {
            #pragma unroll
            for (int kh = 0; kh < 3; kh++) {
                const float* rp = &s_in[(cil * 4 + r + kh) * 130 + col];
                #pragma unroll
                for (int kw = 0; kw < 3; kw++) {
                    float iv = rp[kw];
                    float4 wv = *(const float4*)&s_w[((ci0 + cil) * 9 + kh * 3 + kw) * 4];
                    a0 = fmaf(wv.x, iv, a0);
                    a1 = fmaf(wv.y, iv, a1);
                    a2 = fmaf(wv.z, iv, a2);
                }
            }
        }
        __syncthreads();
    }
    float lsum = 0.f;
    float accs[3] = {a0, a1, a2};
    #pragma unroll
    for (int co = 0; co < 3; co++) {
        float v = accs[co] + bias[co];
        size_t idx = (((size_t)n * 3 + co) * 128 + oh) * 128 + col;
        out[idx] = v;
        float d = v - x[idx];
        lsum = fmaf(d, d, lsum);
    }
    red[tid] = lsum;
    __syncthreads();
    for (int s = 128; s > 0; s >>= 1) {
        if (tid < s) red[tid] += red[tid + s];
        __syncthreads();
    }
    if (tid == 0) rec_part[(size_t)n * 64 + blockIdx.x] = red[0];
}

__global__ void __launch_bounds__(256) finalize_k(const float* __restrict__ rec_part,
                                                  const float* __restrict__ vq_part,
                                                  float* __restrict__ out)
{
    __shared__ double rA[256], rB[256];
    const int tid = threadIdx.x;
    double s = 0.0;
    for (int t = tid; t < 4096; t += 256) s += (double)rec_part[t];
    rA[tid] = s;
    rB[tid] = (double)vq_part[tid];
    __syncthreads();
    for (int st = 128; st > 0; st >>= 1) {
        if (tid < st) { rA[tid] += rA[tid + st]; rB[tid] += rB[tid + st]; }
        __syncthreads();
    }
    if (tid == 0) {
        double recon = rA[0] / 3145728.0;
        double vq    = 1.25 * rB[0] / 4194304.0;
        out[3145728] = (float)(recon + vq);
        out[3145729] = (float)recon;
        out[3145730] = (float)vq;
    }
}

extern "C" void kernel_launch(void* const* d_in, const int* in_sizes, int n_in,
                              void* d_out, int out_size)
{
    (void)in_sizes; (void)n_in; (void)out_size;
    const float* x   = (const float*)d_in[0];
    const float* ew1 = (const float*)d_in[1];
    const float* eb1 = (const float*)d_in[2];
    const float* ew2 = (const float*)d_in[3];
    const float* eb2 = (const float*)d_in[4];
    const float* ew3 = (const float*)d_in[5];
    const float* eb3 = (const float*)d_in[6];
    const float* cb  = (const float*)d_in[7];
    const float* dw1 = (const float*)d_in[8];
    const float* db1 = (const float*)d_in[9];
    const float* dw2 = (const float*)d_in[10];
    const float* db2 = (const float*)d_in[11];
    const float* dw3 = (const float*)d_in[12];
    const float* db3 = (const float*)d_in[13];
    float* out = (float*)d_out;

    void *h1, *h2, *ze, *zq, *dd1, *dd2, *vqp, *recp;
    void *w1t, *w2t, *w3t, *w3dt, *bw1, *bw2;
    cudaGetSymbolAddress(&h1,  g_h1);
    cudaGetSymbolAddress(&h2,  g_h2);
    cudaGetSymbolAddress(&ze,  g_ze);
    cudaGetSymbolAddress(&zq,  g_zq);
    cudaGetSymbolAddress(&dd1, g_d1);
    cudaGetSymbolAddress(&dd2, g_d2);
    cudaGetSymbolAddress(&vqp,  g_vq_part);
    cudaGetSymbolAddress(&recp, g_rec_part);
    cudaGetSymbolAddress(&w1t,  g_w1t);
    cudaGetSymbolAddress(&w2t,  g_w2t);
    cudaGetSymbolAddress(&w3t,  g_w3t);
    cudaGetSymbolAddress(&w3dt, g_w3dt);
    cudaGetSymbolAddress(&bw1,  g_bw1);
    cudaGetSymbolAddress(&bw2,  g_bw2);

    const int SM_E1 = (1028 + 3 * 64) * 4;
    const int SM_E2 = (128 * 18 * 19 + 64 * 128) * 4;
    const int SM_E3 = (128 * 10 * 11 + 128 * 64) * 4;
    const int SM_M1 = 64 * 180 * 4 + 4 * 18432;    // 119808
    const int SM_M2 = 128 * 180 * 4 + 4 * 18432;   // 165888
    const int SM_D3 = (8320 + 128 * 9 * 4) * 4;
    const int SM_VQ = (32768 + 512) * 4;

    cudaFuncSetAttribute((const void*)enc2_k,
                         cudaFuncAttributeMaxDynamicSharedMemorySize, SM_E2);
    cudaFuncSetAttribute((const void*)enc3_k,
                         cudaFuncAttributeMaxDynamicSharedMemorySize, SM_E3);
    cudaFuncSetAttribute((const void*)deconv_mma_k<64,32>,
                         cudaFuncAttributeMaxDynamicSharedMemorySize, SM_M1);
    cudaFuncSetAttribute((const void*)deconv_mma_k<128,64>,
                         cudaFuncAttributeMaxDynamicSharedMemorySize, SM_M2);
    cudaFuncSetAttribute((const void*)vq_k,
                         cudaFuncAttributeMaxDynamicSharedMemorySize, SM_VQ);
    cudaFuncSetAttribute((const void*)dec3_k,
                         cudaFuncAttributeMaxDynamicSharedMemorySize, SM_D3);

    wprep_k<<<256, 256>>>(ew1, ew2, ew3, dw1, dw2, dw3);
    conv_seq<4,2,3,128,128,true><<<dim3(64, 2, NB), 512, SM_E1>>>(
        x, (const float*)w1t, eb1, (float*)h1);
    enc2_k<<<dim3(16, 1, NB), 512, SM_E2>>>(
        (const float*)h1, (const float*)w2t, eb2, (float*)h2);
    enc3_k<<<dim3(16, 1, NB), 256, SM_E3>>>(
        (const float*)h2, (const float*)w3t, eb3, (float*)ze);
    vq_k<<<256, 256, SM_VQ>>>(
        (const float*)ze, cb, (float*)zq, (float*)vqp);
    deconv_mma_k<64,32><<<dim3(8, 4, NB), 256, SM_M1>>>(
        (const float*)zq, (const __nv_bfloat16*)bw1, db1, (float*)dd1);
    deconv_mma_k<128,64><<<dim3(32, 4, NB), 256, SM_M2>>>(
        (const float*)dd1, (const __nv_bfloat16*)bw2, db2, (float*)dd2);
    dec3_k<<<dim3(64, NB), 256, SM_D3>>>(
        (const float*)dd2, (const float*)w3dt, db3, x, out, (float*)recp);
    finalize_k<<<1, 256>>>(
        (const float*)recp, (const float*)vqp, out);
}